// round 16
// baseline (speedup 1.0000x reference)
#include <cuda_runtime.h>
#include <cuda_bf16.h>
#include <cstdint>

#define B_   128
#define S_   128
#define I_   300
#define H_   1024
#define G4_  4096
#define CC_  2
#define PW_  512                   // pair-words per h row

#define WSTRIDE 528                // u32 words per W smem row (512+16 pad; %32==16)
#define SMEM_BYTES (32 * WSTRIDE * 4)   // 67584

__device__ float    d_G[(size_t)S_ * B_ * G4_];           // [s][b][gate*1024+j]
__device__ uint32_t d_hsu[(size_t)(S_ + 1) * B_ * PW_];   // h fragment-direct [q4][row] uint4
__device__ int      d_flags[B_];                          // per-CTA step flags

__device__ __forceinline__ uint32_t f2tf(float x) {
    uint32_t u; asm("cvt.rna.tf32.f32 %0, %1;" : "=r"(u) : "f"(x)); return u;
}
__device__ __forceinline__ uint32_t f2tf_u(uint32_t raw) { return f2tf(__uint_as_float(raw)); }
__device__ __forceinline__ uint32_t smem_u32(const void* p) {
    uint32_t a;
    asm("{ .reg .u64 t; cvta.to.shared.u64 t, %1; cvt.u32.u64 %0, t; }" : "=r"(a) : "l"(p));
    return a;
}
__device__ __forceinline__ void mma_tf32(float c[4], const uint32_t a[4], const uint32_t b[2]) {
    asm volatile(
        "mma.sync.aligned.m16n8k8.row.col.f32.tf32.tf32.f32 "
        "{%0,%1,%2,%3}, {%4,%5,%6,%7}, {%8,%9}, {%0,%1,%2,%3};\n"
        : "+f"(c[0]), "+f"(c[1]), "+f"(c[2]), "+f"(c[3])
        : "r"(a[0]), "r"(a[1]), "r"(a[2]), "r"(a[3]), "r"(b[0]), "r"(b[1]));
}
__device__ __forceinline__ void mma_bf16(float c[4], const uint32_t a[4], const uint32_t b[2]) {
    asm volatile(
        "mma.sync.aligned.m16n8k16.row.col.f32.bf16.bf16.f32 "
        "{%0,%1,%2,%3}, {%4,%5,%6,%7}, {%8,%9}, {%0,%1,%2,%3};\n"
        : "+f"(c[0]), "+f"(c[1]), "+f"(c[2]), "+f"(c[3])
        : "r"(a[0]), "r"(a[1]), "r"(a[2]), "r"(a[3]), "r"(b[0]), "r"(b[1]));
}
__device__ __forceinline__ float tanh_ap(float x) {
    float y; asm("tanh.approx.f32 %0, %1;" : "=f"(y) : "f"(x)); return y;
}
__device__ __forceinline__ float sigf(float x)   { return fmaf(0.5f, tanh_ap(0.5f * x), 0.5f); }
__device__ __forceinline__ float tanhf_(float x) { return tanh_ap(x); }
__device__ __forceinline__ void flag_set(int bid, int v) {
    asm volatile("st.release.gpu.global.b32 [%0], %1;" :: "l"(&d_flags[bid]), "r"(v) : "memory");
}
__device__ __forceinline__ int flag_get(int i) {
    int v;
    asm volatile("ld.acquire.gpu.global.b32 %0, [%1];" : "=r"(v) : "l"(&d_flags[i]) : "memory");
    return v;
}
__device__ __forceinline__ void cpa16(uint32_t dst, const void* src, int src_bytes) {
    asm volatile("cp.async.cg.shared.global [%0], [%1], 16, %2;"
                 :: "r"(dst), "l"(src), "r"(src_bytes) : "memory");
}

__global__ void init_state() {
    int idx = blockIdx.x * 256 + threadIdx.x;
    if (idx < B_ * PW_) d_hsu[idx] = 0u;
    if (idx < B_) d_flags[idx] = 0;
}

// ---------------- input-path GEMM (R10 tf32 core, known-good) ----------------
__global__ __launch_bounds__(256) void embed_gemm(
    const int* __restrict__ x, const float* __restrict__ embW,
    const float* __restrict__ W_ih, const float* __restrict__ b_ih,
    const float* __restrict__ b_hh)
{
    __shared__ uint32_t As[2][128][20];
    __shared__ uint32_t Bs[2][64][20];
    __shared__ int toks[128];

    const int tid = threadIdx.x;
    const int s   = blockIdx.x;
    const int n0  = blockIdx.y * 64;

    if (tid < 128) toks[tid] = x[tid * S_ + s];

    const int w  = tid >> 5, lane = tid & 31;
    const int wm = w >> 1,   wn   = w & 1;
    const int gr = lane >> 2, gc  = lane & 3;
    const int mw = wm * 32,  nw   = wn * 32;

    const int arow = tid >> 1, akb = (tid & 1) * 8;
    const int brow = tid >> 2, bkb = (tid & 3) * 4;

    __syncthreads();

    const float* aptr = embW + (size_t)toks[arow] * I_;
    const float* bptr = W_ih + (size_t)(n0 + brow) * I_;

    auto stage = [&](int kt, int bi) {
        const int k0 = kt * 16;
#pragma unroll
        for (int q = 0; q < 2; q++) {
            int kq = k0 + akb + q * 4;
            int sz = (I_ - kq) * 4; sz = sz < 0 ? 0 : (sz > 16 ? 16 : sz);
            cpa16(smem_u32(&As[bi][arow][akb + q * 4]), aptr + (sz ? kq : 0), sz);
        }
        {
            int kq = k0 + bkb;
            int sz = (I_ - kq) * 4; sz = sz < 0 ? 0 : (sz > 16 ? 16 : sz);
            cpa16(smem_u32(&Bs[bi][brow][bkb]), bptr + (sz ? kq : 0), sz);
        }
        asm volatile("cp.async.commit_group;" ::: "memory");
    };

    float acc[2][4][4];
#pragma unroll
    for (int mi = 0; mi < 2; mi++)
#pragma unroll
        for (int ni = 0; ni < 4; ni++)
#pragma unroll
            for (int q = 0; q < 4; q++) acc[mi][ni][q] = 0.0f;

    stage(0, 0);

    for (int kt = 0; kt < 19; kt++) {
        const int bi = kt & 1;
        if (kt < 18) {
            stage(kt + 1, bi ^ 1);
            asm volatile("cp.async.wait_group 1;" ::: "memory");
        } else {
            asm volatile("cp.async.wait_group 0;" ::: "memory");
        }
        __syncthreads();

#pragma unroll
        for (int ks = 0; ks < 2; ks++) {
            uint32_t a[2][4], b[4][2];
#pragma unroll
            for (int mi = 0; mi < 2; mi++) {
                a[mi][0] = f2tf_u(As[bi][mw + mi * 16 + gr][ks * 8 + gc]);
                a[mi][1] = f2tf_u(As[bi][mw + mi * 16 + 8 + gr][ks * 8 + gc]);
                a[mi][2] = f2tf_u(As[bi][mw + mi * 16 + gr][ks * 8 + 4 + gc]);
                a[mi][3] = f2tf_u(As[bi][mw + mi * 16 + 8 + gr][ks * 8 + 4 + gc]);
            }
#pragma unroll
            for (int ni = 0; ni < 4; ni++) {
                b[ni][0] = f2tf_u(Bs[bi][nw + ni * 8 + gr][ks * 8 + gc]);
                b[ni][1] = f2tf_u(Bs[bi][nw + ni * 8 + gr][ks * 8 + 4 + gc]);
            }
#pragma unroll
            for (int mi = 0; mi < 2; mi++)
#pragma unroll
                for (int ni = 0; ni < 4; ni++)
                    mma_tf32(acc[mi][ni], a[mi], b[ni]);
        }
        __syncthreads();
    }

#pragma unroll
    for (int mi = 0; mi < 2; mi++) {
        const int m0 = mw + mi * 16 + gr;
#pragma unroll
        for (int ni = 0; ni < 4; ni++) {
            const int n = n0 + nw + ni * 8 + gc * 2;
            const float bias0 = b_ih[n] + b_hh[n];
            const float bias1 = b_ih[n + 1] + b_hh[n + 1];
            size_t base0 = ((size_t)s * B_ + m0) * G4_ + n;
            size_t base1 = ((size_t)s * B_ + m0 + 8) * G4_ + n;
            d_G[base0]     = acc[mi][ni][0] + bias0;
            d_G[base0 + 1] = acc[mi][ni][1] + bias1;
            d_G[base1]     = acc[mi][ni][2] + bias0;
            d_G[base1 + 1] = acc[mi][ni][3] + bias1;
        }
    }
}

// ---------------- persistent recurrence (exact R10 inner loop; flag barrier) ----------------
extern __shared__ uint32_t smem_dynu[];

__global__ void __launch_bounds__(256, 1) lstm_persistent(const float* __restrict__ W_hh)
{
    uint32_t* Ws = smem_dynu;    // [32][WSTRIDE]

    const int tid = threadIdx.x;
    const int bid = blockIdx.x;
    const int c0  = bid * 8;

    const int w  = tid >> 5, lane = tid & 31;
    const int gr = lane >> 2, gc = lane & 3;
    const int mw = (w >> 1) * 32;
    const int nw = (w & 1) * 16;

    for (int i = tid; i < 32 * PW_; i += 256) {
        int p = i >> 9, wq = i & 511;
        int gate = ((p >> 3) & 1) * 2 + (p & 1);
        int jloc = ((p >> 4) & 1) * 4 + ((p >> 1) & 3);
        const float* wr = W_hh + (size_t)(gate * H_ + c0 + jloc) * H_ + 2 * wq;
        __nv_bfloat162 pk = __floats2bfloat162_rn(wr[0], wr[1]);
        Ws[p * WSTRIDE + wq] = *reinterpret_cast<uint32_t*>(&pk);
    }
    __syncthreads();

    const int jglob = c0 + (w & 1) * 4 + gc;
    const int pj    = jglob >> 1;
    const int q4w   = pj >> 2;
    const int wsel  = pj & 3;
    const int half  = jglob & 1;

    float cReg[4] = {0.0f, 0.0f, 0.0f, 0.0f};

    for (int t = 0; t < S_; t++) {
        const uint4* hf = reinterpret_cast<const uint4*>(d_hsu + (size_t)t * (B_ * PW_));

        float gv[2][2][4];
        {
            const float* Gt = d_G + (size_t)t * B_ * G4_;
#pragma unroll
            for (int mi = 0; mi < 2; mi++)
#pragma unroll
                for (int rs = 0; rs < 2; rs++) {
                    int r = mw + mi * 16 + gr + rs * 8;
                    const float* Gr = Gt + (size_t)r * G4_ + jglob;
#pragma unroll
                    for (int g = 0; g < 4; g++) gv[mi][rs][g] = Gr[g * H_];
                }
        }

        float acc[2][2][4];
#pragma unroll
        for (int mi = 0; mi < 2; mi++)
#pragma unroll
            for (int ni = 0; ni < 2; ni++)
#pragma unroll
                for (int q = 0; q < 4; q++) acc[mi][ni][q] = 0.0f;

        uint4 abuf[2][16];
        auto lda = [&](int c, int buf) {
#pragma unroll
            for (int gl = 0; gl < 4; gl++)
#pragma unroll
                for (int mi = 0; mi < 2; mi++)
#pragma unroll
                    for (int rs = 0; rs < 2; rs++)
                        abuf[buf][gl * 4 + mi * 2 + rs] =
                            hf[(size_t)(c * 16 + gl * 4 + gc) * 128 + mw + mi * 16 + rs * 8 + gr];
        };

        lda(0, 0);

        for (int c = 0; c < 8; c++) {
            const int buf = c & 1;
            if (c < 7) lda(c + 1, buf ^ 1);

#pragma unroll
            for (int gl = 0; gl < 4; gl++) {
                uint4 av0 = abuf[buf][gl * 4 + 0];
                uint4 av1 = abuf[buf][gl * 4 + 1];
                uint4 av2 = abuf[buf][gl * 4 + 2];
                uint4 av3 = abuf[buf][gl * 4 + 3];
                const int wfull = c * 64 + gl * 16 + gc * 4;
                uint4 bv0 = *reinterpret_cast<const uint4*>(Ws + (nw + gr) * WSTRIDE + wfull);
                uint4 bv1 = *reinterpret_cast<const uint4*>(Ws + (nw + 8 + gr) * WSTRIDE + wfull);
                {
                    uint32_t b0[2] = {bv0.x, bv0.y};
                    uint32_t b1[2] = {bv1.x, bv1.y};
                    uint32_t a0[4] = {av0.x, av1.x, av0.y, av1.y};
                    uint32_t a1[4] = {av2.x, av3.x, av2.y, av3.y};
                    mma_bf16(acc[0][0], a0, b0); mma_bf16(acc[0][1], a0, b1);
                    mma_bf16(acc[1][0], a1, b0); mma_bf16(acc[1][1], a1, b1);
                }
                {
                    uint32_t b0[2] = {bv0.z, bv0.w};
                    uint32_t b1[2] = {bv1.z, bv1.w};
                    uint32_t a0[4] = {av0.z, av1.z, av0.w, av1.w};
                    uint32_t a1[4] = {av2.z, av3.z, av2.w, av3.w};
                    mma_bf16(acc[0][0], a0, b0); mma_bf16(acc[0][1], a0, b1);
                    mma_bf16(acc[1][0], a1, b0); mma_bf16(acc[1][1], a1, b1);
                }
            }
        }

        __nv_bfloat16* hout = reinterpret_cast<__nv_bfloat16*>(
            d_hsu + (size_t)(t + 1) * (B_ * PW_));
#pragma unroll
        for (int mi = 0; mi < 2; mi++)
#pragma unroll
            for (int rs = 0; rs < 2; rs++) {
                const int r = mw + mi * 16 + gr + rs * 8;
                const float ig = acc[mi][0][rs * 2]     + gv[mi][rs][0];
                const float fg = acc[mi][0][rs * 2 + 1] + gv[mi][rs][1];
                const float gg = acc[mi][1][rs * 2]     + gv[mi][rs][2];
                const float og = acc[mi][1][rs * 2 + 1] + gv[mi][rs][3];
                const int ci = mi * 2 + rs;
                const float cn = sigf(fg) * cReg[ci] + sigf(ig) * tanhf_(gg);
                cReg[ci] = cn;
                const float h = sigf(og) * tanhf_(cn);
                hout[(size_t)((q4w * 128 + r) * 4 + wsel) * 2 + half] = __float2bfloat16_rn(h);
            }

        // distributed flag barrier: arrival = release store to own slot,
        // wait = threads 0..127 poll independent slots (acquire)
        __syncthreads();
        if (tid == 0) flag_set(bid, t + 1);
        if (tid < 128) {
            while (flag_get(tid) < t + 1) { __nanosleep(40); }
        }
        __syncthreads();
    }
}

// ---------------- output projection (R13, measured 15us) ----------------
__global__ __launch_bounds__(512) void out_proj(
    const int* __restrict__ lengths, const float* __restrict__ linW,
    const float* __restrict__ linb, float* __restrict__ out)
{
    __shared__ float w0[H_], w1[H_];
    __shared__ float p0[4][128], p1[4][128];
    const int s  = blockIdx.x;
    const int t  = threadIdx.x;
    const int b  = t & 127;
    const int qq = t >> 7;

    for (int i = t; i < H_; i += 512) { w0[i] = linW[i]; w1[i] = linW[H_ + i]; }
    __syncthreads();

    const uint4* __restrict__ h4 = reinterpret_cast<const uint4*>(
        d_hsu + (size_t)(s + 1) * (B_ * PW_));
    float s0 = 0.0f, s1 = 0.0f;
#pragma unroll 8
    for (int q4 = qq * 32; q4 < qq * 32 + 32; q4++) {
        uint4 u = h4[(size_t)q4 * 128 + b];
        const uint32_t wds[4] = {u.x, u.y, u.z, u.w};
        const int k0 = 8 * q4;
#pragma unroll
        for (int j = 0; j < 4; j++) {
            __nv_bfloat162 pk = *reinterpret_cast<const __nv_bfloat162*>(&wds[j]);
            const float h0 = __bfloat162float(pk.x), h1 = __bfloat162float(pk.y);
            s0 += h0 * w0[k0 + 2 * j] + h1 * w0[k0 + 2 * j + 1];
            s1 += h0 * w1[k0 + 2 * j] + h1 * w1[k0 + 2 * j + 1];
        }
    }
    p0[qq][b] = s0; p1[qq][b] = s1;
    __syncthreads();

    if (t < 128) {
        float r0 = p0[0][t] + p0[1][t] + p0[2][t] + p0[3][t];
        float r1 = p1[0][t] + p1[1][t] + p1[2][t] + p1[3][t];
        float* orow = out + ((size_t)t * S_ + s) * CC_;
        if (s < lengths[t]) {
            orow[0] = r0 + linb[0];
            orow[1] = r1 + linb[1];
        } else {
            orow[0] = 1.0f;
            orow[1] = 0.0f;
        }
    }
}

extern "C" void kernel_launch(void* const* d_in, const int* in_sizes, int n_in,
                              void* d_out, int out_size) {
    const int*   x       = (const int*)d_in[0];
    const int*   lengths = (const int*)d_in[1];
    const float* embW    = (const float*)d_in[2];
    const float* W_ih    = (const float*)d_in[3];
    const float* W_hh    = (const float*)d_in[4];
    const float* b_ih    = (const float*)d_in[5];
    const float* b_hh    = (const float*)d_in[6];
    const float* linW    = (const float*)d_in[7];
    const float* linb    = (const float*)d_in[8];
    float*       out     = (float*)d_out;

    static bool attr_done = false;
    if (!attr_done) {
        cudaFuncSetAttribute(lstm_persistent,
                             cudaFuncAttributeMaxDynamicSharedMemorySize, SMEM_BYTES);
        attr_done = true;
    }

    init_state<<<512, 256>>>();
    embed_gemm<<<dim3(128, 64), 256>>>(x, embW, W_ih, b_ih, b_hh);
    lstm_persistent<<<128, 256, SMEM_BYTES>>>(W_hh);
    out_proj<<<128, 512>>>(lengths, linW, linb, out);
}

// round 17
// speedup vs baseline: 1.2600x; 1.2600x over previous
#include <cuda_runtime.h>
#include <cuda_bf16.h>
#include <cstdint>

#define B_   128
#define S_   128
#define I_   300
#define H_   1024
#define G4_  4096
#define CC_  2
#define PW_  512                   // pair-words per h row

#define WSTRIDE 528                // u32 words per W smem row (512+16 pad; %32==16)
#define SMEM_BYTES (32 * WSTRIDE * 4)   // 67584

__device__ float    d_G[(size_t)S_ * B_ * G4_];           // [s][b][gate*1024+j]
__device__ uint32_t d_hsu[(size_t)(S_ + 1) * B_ * PW_];   // h fragment-direct [q4][row] uint4
__device__ int      d_ctr;

__device__ __forceinline__ uint32_t f2tf(float x) {
    uint32_t u; asm("cvt.rna.tf32.f32 %0, %1;" : "=r"(u) : "f"(x)); return u;
}
__device__ __forceinline__ uint32_t f2tf_u(uint32_t raw) { return f2tf(__uint_as_float(raw)); }
__device__ __forceinline__ uint32_t smem_u32(const void* p) {
    uint32_t a;
    asm("{ .reg .u64 t; cvta.to.shared.u64 t, %1; cvt.u32.u64 %0, t; }" : "=r"(a) : "l"(p));
    return a;
}
__device__ __forceinline__ void mma_tf32(float c[4], const uint32_t a[4], const uint32_t b[2]) {
    asm volatile(
        "mma.sync.aligned.m16n8k8.row.col.f32.tf32.tf32.f32 "
        "{%0,%1,%2,%3}, {%4,%5,%6,%7}, {%8,%9}, {%0,%1,%2,%3};\n"
        : "+f"(c[0]), "+f"(c[1]), "+f"(c[2]), "+f"(c[3])
        : "r"(a[0]), "r"(a[1]), "r"(a[2]), "r"(a[3]), "r"(b[0]), "r"(b[1]));
}
__device__ __forceinline__ void mma_bf16(float c[4], const uint32_t a[4], const uint32_t b[2]) {
    asm volatile(
        "mma.sync.aligned.m16n8k16.row.col.f32.bf16.bf16.f32 "
        "{%0,%1,%2,%3}, {%4,%5,%6,%7}, {%8,%9}, {%0,%1,%2,%3};\n"
        : "+f"(c[0]), "+f"(c[1]), "+f"(c[2]), "+f"(c[3])
        : "r"(a[0]), "r"(a[1]), "r"(a[2]), "r"(a[3]), "r"(b[0]), "r"(b[1]));
}
__device__ __forceinline__ float tanh_ap(float x) {
    float y; asm("tanh.approx.f32 %0, %1;" : "=f"(y) : "f"(x)); return y;
}
__device__ __forceinline__ float sigf(float x)   { return fmaf(0.5f, tanh_ap(0.5f * x), 0.5f); }
__device__ __forceinline__ float tanhf_(float x) { return tanh_ap(x); }
__device__ __forceinline__ void bar_arrive() {
    asm volatile("red.release.gpu.global.add.s32 [%0], 1;" :: "l"(&d_ctr) : "memory");
}
__device__ __forceinline__ int bar_poll() {
    int v;
    asm volatile("ld.acquire.gpu.global.b32 %0, [%1];" : "=r"(v) : "l"(&d_ctr) : "memory");
    return v;
}
__device__ __forceinline__ void cpa16(uint32_t dst, const void* src, int src_bytes) {
    asm volatile("cp.async.cg.shared.global [%0], [%1], 16, %2;"
                 :: "r"(dst), "l"(src), "r"(src_bytes) : "memory");
}

__global__ void init_state() {
    int idx = blockIdx.x * 256 + threadIdx.x;
    if (idx < B_ * PW_) d_hsu[idx] = 0u;
    if (idx == 0) d_ctr = 0;
}

// ---------------- input-path GEMM (R10 tf32 core, known-good) ----------------
__global__ __launch_bounds__(256) void embed_gemm(
    const int* __restrict__ x, const float* __restrict__ embW,
    const float* __restrict__ W_ih, const float* __restrict__ b_ih,
    const float* __restrict__ b_hh)
{
    __shared__ uint32_t As[2][128][20];
    __shared__ uint32_t Bs[2][64][20];
    __shared__ int toks[128];

    const int tid = threadIdx.x;
    const int s   = blockIdx.x;
    const int n0  = blockIdx.y * 64;

    if (tid < 128) toks[tid] = x[tid * S_ + s];

    const int w  = tid >> 5, lane = tid & 31;
    const int wm = w >> 1,   wn   = w & 1;
    const int gr = lane >> 2, gc  = lane & 3;
    const int mw = wm * 32,  nw   = wn * 32;

    const int arow = tid >> 1, akb = (tid & 1) * 8;
    const int brow = tid >> 2, bkb = (tid & 3) * 4;

    __syncthreads();

    const float* aptr = embW + (size_t)toks[arow] * I_;
    const float* bptr = W_ih + (size_t)(n0 + brow) * I_;

    auto stage = [&](int kt, int bi) {
        const int k0 = kt * 16;
#pragma unroll
        for (int q = 0; q < 2; q++) {
            int kq = k0 + akb + q * 4;
            int sz = (I_ - kq) * 4; sz = sz < 0 ? 0 : (sz > 16 ? 16 : sz);
            cpa16(smem_u32(&As[bi][arow][akb + q * 4]), aptr + (sz ? kq : 0), sz);
        }
        {
            int kq = k0 + bkb;
            int sz = (I_ - kq) * 4; sz = sz < 0 ? 0 : (sz > 16 ? 16 : sz);
            cpa16(smem_u32(&Bs[bi][brow][bkb]), bptr + (sz ? kq : 0), sz);
        }
        asm volatile("cp.async.commit_group;" ::: "memory");
    };

    float acc[2][4][4];
#pragma unroll
    for (int mi = 0; mi < 2; mi++)
#pragma unroll
        for (int ni = 0; ni < 4; ni++)
#pragma unroll
            for (int q = 0; q < 4; q++) acc[mi][ni][q] = 0.0f;

    stage(0, 0);

    for (int kt = 0; kt < 19; kt++) {
        const int bi = kt & 1;
        if (kt < 18) {
            stage(kt + 1, bi ^ 1);
            asm volatile("cp.async.wait_group 1;" ::: "memory");
        } else {
            asm volatile("cp.async.wait_group 0;" ::: "memory");
        }
        __syncthreads();

#pragma unroll
        for (int ks = 0; ks < 2; ks++) {
            uint32_t a[2][4], b[4][2];
#pragma unroll
            for (int mi = 0; mi < 2; mi++) {
                a[mi][0] = f2tf_u(As[bi][mw + mi * 16 + gr][ks * 8 + gc]);
                a[mi][1] = f2tf_u(As[bi][mw + mi * 16 + 8 + gr][ks * 8 + gc]);
                a[mi][2] = f2tf_u(As[bi][mw + mi * 16 + gr][ks * 8 + 4 + gc]);
                a[mi][3] = f2tf_u(As[bi][mw + mi * 16 + 8 + gr][ks * 8 + 4 + gc]);
            }
#pragma unroll
            for (int ni = 0; ni < 4; ni++) {
                b[ni][0] = f2tf_u(Bs[bi][nw + ni * 8 + gr][ks * 8 + gc]);
                b[ni][1] = f2tf_u(Bs[bi][nw + ni * 8 + gr][ks * 8 + 4 + gc]);
            }
#pragma unroll
            for (int mi = 0; mi < 2; mi++)
#pragma unroll
                for (int ni = 0; ni < 4; ni++)
                    mma_tf32(acc[mi][ni], a[mi], b[ni]);
        }
        __syncthreads();
    }

#pragma unroll
    for (int mi = 0; mi < 2; mi++) {
        const int m0 = mw + mi * 16 + gr;
#pragma unroll
        for (int ni = 0; ni < 4; ni++) {
            const int n = n0 + nw + ni * 8 + gc * 2;
            const float bias0 = b_ih[n] + b_hh[n];
            const float bias1 = b_ih[n + 1] + b_hh[n + 1];
            size_t base0 = ((size_t)s * B_ + m0) * G4_ + n;
            size_t base1 = ((size_t)s * B_ + m0 + 8) * G4_ + n;
            d_G[base0]     = acc[mi][ni][0] + bias0;
            d_G[base0 + 1] = acc[mi][ni][1] + bias1;
            d_G[base1]     = acc[mi][ni][2] + bias0;
            d_G[base1 + 1] = acc[mi][ni][3] + bias1;
        }
    }
}

// ---------------- persistent recurrence (exact R10: counter barrier) ----------------
extern __shared__ uint32_t smem_dynu[];

__global__ void __launch_bounds__(256, 1) lstm_persistent(const float* __restrict__ W_hh)
{
    uint32_t* Ws = smem_dynu;    // [32][WSTRIDE]

    const int tid = threadIdx.x;
    const int bid = blockIdx.x;
    const int c0  = bid * 8;

    const int w  = tid >> 5, lane = tid & 31;
    const int gr = lane >> 2, gc = lane & 3;
    const int mw = (w >> 1) * 32;
    const int nw = (w & 1) * 16;

    for (int i = tid; i < 32 * PW_; i += 256) {
        int p = i >> 9, wq = i & 511;
        int gate = ((p >> 3) & 1) * 2 + (p & 1);
        int jloc = ((p >> 4) & 1) * 4 + ((p >> 1) & 3);
        const float* wr = W_hh + (size_t)(gate * H_ + c0 + jloc) * H_ + 2 * wq;
        __nv_bfloat162 pk = __floats2bfloat162_rn(wr[0], wr[1]);
        Ws[p * WSTRIDE + wq] = *reinterpret_cast<uint32_t*>(&pk);
    }
    __syncthreads();

    const int jglob = c0 + (w & 1) * 4 + gc;
    const int pj    = jglob >> 1;
    const int q4w   = pj >> 2;
    const int wsel  = pj & 3;
    const int half  = jglob & 1;

    float cReg[4] = {0.0f, 0.0f, 0.0f, 0.0f};

    for (int t = 0; t < S_; t++) {
        const uint4* hf = reinterpret_cast<const uint4*>(d_hsu + (size_t)t * (B_ * PW_));

        float gv[2][2][4];
        {
            const float* Gt = d_G + (size_t)t * B_ * G4_;
#pragma unroll
            for (int mi = 0; mi < 2; mi++)
#pragma unroll
                for (int rs = 0; rs < 2; rs++) {
                    int r = mw + mi * 16 + gr + rs * 8;
                    const float* Gr = Gt + (size_t)r * G4_ + jglob;
#pragma unroll
                    for (int g = 0; g < 4; g++) gv[mi][rs][g] = Gr[g * H_];
                }
        }

        float acc[2][2][4];
#pragma unroll
        for (int mi = 0; mi < 2; mi++)
#pragma unroll
            for (int ni = 0; ni < 2; ni++)
#pragma unroll
                for (int q = 0; q < 4; q++) acc[mi][ni][q] = 0.0f;

        uint4 abuf[2][16];
        auto lda = [&](int c, int buf) {
#pragma unroll
            for (int gl = 0; gl < 4; gl++)
#pragma unroll
                for (int mi = 0; mi < 2; mi++)
#pragma unroll
                    for (int rs = 0; rs < 2; rs++)
                        abuf[buf][gl * 4 + mi * 2 + rs] =
                            hf[(size_t)(c * 16 + gl * 4 + gc) * 128 + mw + mi * 16 + rs * 8 + gr];
        };

        lda(0, 0);

        for (int c = 0; c < 8; c++) {
            const int buf = c & 1;
            if (c < 7) lda(c + 1, buf ^ 1);

#pragma unroll
            for (int gl = 0; gl < 4; gl++) {
                uint4 av0 = abuf[buf][gl * 4 + 0];
                uint4 av1 = abuf[buf][gl * 4 + 1];
                uint4 av2 = abuf[buf][gl * 4 + 2];
                uint4 av3 = abuf[buf][gl * 4 + 3];
                const int wfull = c * 64 + gl * 16 + gc * 4;
                uint4 bv0 = *reinterpret_cast<const uint4*>(Ws + (nw + gr) * WSTRIDE + wfull);
                uint4 bv1 = *reinterpret_cast<const uint4*>(Ws + (nw + 8 + gr) * WSTRIDE + wfull);
                {
                    uint32_t b0[2] = {bv0.x, bv0.y};
                    uint32_t b1[2] = {bv1.x, bv1.y};
                    uint32_t a0[4] = {av0.x, av1.x, av0.y, av1.y};
                    uint32_t a1[4] = {av2.x, av3.x, av2.y, av3.y};
                    mma_bf16(acc[0][0], a0, b0); mma_bf16(acc[0][1], a0, b1);
                    mma_bf16(acc[1][0], a1, b0); mma_bf16(acc[1][1], a1, b1);
                }
                {
                    uint32_t b0[2] = {bv0.z, bv0.w};
                    uint32_t b1[2] = {bv1.z, bv1.w};
                    uint32_t a0[4] = {av0.z, av1.z, av0.w, av1.w};
                    uint32_t a1[4] = {av2.z, av3.z, av2.w, av3.w};
                    mma_bf16(acc[0][0], a0, b0); mma_bf16(acc[0][1], a0, b1);
                    mma_bf16(acc[1][0], a1, b0); mma_bf16(acc[1][1], a1, b1);
                }
            }
        }

        __nv_bfloat16* hout = reinterpret_cast<__nv_bfloat16*>(
            d_hsu + (size_t)(t + 1) * (B_ * PW_));
#pragma unroll
        for (int mi = 0; mi < 2; mi++)
#pragma unroll
            for (int rs = 0; rs < 2; rs++) {
                const int r = mw + mi * 16 + gr + rs * 8;
                const float ig = acc[mi][0][rs * 2]     + gv[mi][rs][0];
                const float fg = acc[mi][0][rs * 2 + 1] + gv[mi][rs][1];
                const float gg = acc[mi][1][rs * 2]     + gv[mi][rs][2];
                const float og = acc[mi][1][rs * 2 + 1] + gv[mi][rs][3];
                const int ci = mi * 2 + rs;
                const float cn = sigf(fg) * cReg[ci] + sigf(ig) * tanhf_(gg);
                cReg[ci] = cn;
                const float h = sigf(og) * tanhf_(cn);
                hout[(size_t)((q4w * 128 + r) * 4 + wsel) * 2 + half] = __float2bfloat16_rn(h);
            }

        __syncthreads();
        if (tid == 0) {
            bar_arrive();
            const int tgt = 128 * (t + 1);
            while (bar_poll() < tgt) { __nanosleep(40); }
        }
        __syncthreads();
    }
}

// ---------------- output projection (R13, measured ~15us) ----------------
__global__ __launch_bounds__(512) void out_proj(
    const int* __restrict__ lengths, const float* __restrict__ linW,
    const float* __restrict__ linb, float* __restrict__ out)
{
    __shared__ float w0[H_], w1[H_];
    __shared__ float p0[4][128], p1[4][128];
    const int s  = blockIdx.x;
    const int t  = threadIdx.x;
    const int b  = t & 127;
    const int qq = t >> 7;

    for (int i = t; i < H_; i += 512) { w0[i] = linW[i]; w1[i] = linW[H_ + i]; }
    __syncthreads();

    const uint4* __restrict__ h4 = reinterpret_cast<const uint4*>(
        d_hsu + (size_t)(s + 1) * (B_ * PW_));
    float s0 = 0.0f, s1 = 0.0f;
#pragma unroll 8
    for (int q4 = qq * 32; q4 < qq * 32 + 32; q4++) {
        uint4 u = h4[(size_t)q4 * 128 + b];
        const uint32_t wds[4] = {u.x, u.y, u.z, u.w};
        const int k0 = 8 * q4;
#pragma unroll
        for (int j = 0; j < 4; j++) {
            __nv_bfloat162 pk = *reinterpret_cast<const __nv_bfloat162*>(&wds[j]);
            const float h0 = __bfloat162float(pk.x), h1 = __bfloat162float(pk.y);
            s0 += h0 * w0[k0 + 2 * j] + h1 * w0[k0 + 2 * j + 1];
            s1 += h0 * w1[k0 + 2 * j] + h1 * w1[k0 + 2 * j + 1];
        }
    }
    p0[qq][b] = s0; p1[qq][b] = s1;
    __syncthreads();

    if (t < 128) {
        float r0 = p0[0][t] + p0[1][t] + p0[2][t] + p0[3][t];
        float r1 = p1[0][t] + p1[1][t] + p1[2][t] + p1[3][t];
        float* orow = out + ((size_t)t * S_ + s) * CC_;
        if (s < lengths[t]) {
            orow[0] = r0 + linb[0];
            orow[1] = r1 + linb[1];
        } else {
            orow[0] = 1.0f;
            orow[1] = 0.0f;
        }
    }
}

extern "C" void kernel_launch(void* const* d_in, const int* in_sizes, int n_in,
                              void* d_out, int out_size) {
    const int*   x       = (const int*)d_in[0];
    const int*   lengths = (const int*)d_in[1];
    const float* embW    = (const float*)d_in[2];
    const float* W_ih    = (const float*)d_in[3];
    const float* W_hh    = (const float*)d_in[4];
    const float* b_ih    = (const float*)d_in[5];
    const float* b_hh    = (const float*)d_in[6];
    const float* linW    = (const float*)d_in[7];
    const float* linb    = (const float*)d_in[8];
    float*       out     = (float*)d_out;

    static bool attr_done = false;
    if (!attr_done) {
        cudaFuncSetAttribute(lstm_persistent,
                             cudaFuncAttributeMaxDynamicSharedMemorySize, SMEM_BYTES);
        attr_done = true;
    }

    init_state<<<512, 256>>>();
    embed_gemm<<<dim3(128, 64), 256>>>(x, embW, W_ih, b_ih, b_hh);
    lstm_persistent<<<128, 256, SMEM_BYTES>>>(W_hh);
    out_proj<<<128, 512>>>(lengths, linW, linb, out);
}